// round 8
// baseline (speedup 1.0000x reference)
#include <cuda_runtime.h>
#include <cstdint>

#define KNS 16
#define KNV 8
#define KHE 32
#define KD  40
#define KWN 640
#define KNODES 10000
#define KEDGES 160000
#define KC110 0.5773502691896258f
#define KC111 0.7071067811865476f
#define KEPS  1e-5f

// shared memory layout (bytes)
#define SM_P1 163840                 // after P2 (640*32 float2)
#define SM_B2 172032
#define SM_B1 177152
#define SM_BYTES 177408

#define NTHREADS 512
#define NBLOCKS  148

// ---------------------------------------------------------------------------
// device scratch (static -- no cudaMalloc allowed)
// ---------------------------------------------------------------------------
__device__ float    g_qnode[KNODES * KD];
__device__ float    g_attn[KEDGES];
__device__ float    g_eval[KEDGES];
__device__ float    g_kedge[KD * KEDGES];   // TRANSPOSED [d][e]
__device__ float    g_vedge[KD * KEDGES];   // TRANSPOSED [d][e]
__device__ float    g_efT[KHE * KEDGES];    // TRANSPOSED [j][e]
__device__ unsigned g_maxkey[KNODES];
__device__ float    g_denom[KNODES];
__device__ float    g_upd[KNODES * KD];
__device__ float    g_stats[40];
// per-edge TP coefficients, TRANSPOSED [coef][edge]:
// rows 0..23 = cA, rows 24..119 = tB
__device__ float    g_coef[120 * KEDGES];

// ---------------------------------------------------------------------------
// packed f32x2 helpers (FFMA2 only reachable via PTX)
// ---------------------------------------------------------------------------
__device__ __forceinline__ unsigned long long ffma2(unsigned long long a,
                                                    unsigned long long b,
                                                    unsigned long long c) {
  unsigned long long d;
  asm("fma.rn.f32x2 %0, %1, %2, %3;" : "=l"(d) : "l"(a), "l"(b), "l"(c));
  return d;
}
__device__ __forceinline__ unsigned long long fadd2(unsigned long long a,
                                                    unsigned long long b) {
  unsigned long long d;
  asm("add.rn.f32x2 %0, %1, %2;" : "=l"(d) : "l"(a), "l"(b));
  return d;
}
__device__ __forceinline__ unsigned long long pk2(float lo, float hi) {
  unsigned long long r;
  asm("mov.b64 %0, {%1, %2};" : "=l"(r) : "f"(lo), "f"(hi));
  return r;
}
__device__ __forceinline__ void upk2(unsigned long long v, float& lo, float& hi) {
  asm("mov.b64 {%0, %1}, %2;" : "=f"(lo), "=f"(hi) : "l"(v));
}

// orderable-uint encoding for float atomicMax
__device__ __forceinline__ unsigned fenc(float f) {
  unsigned u = __float_as_uint(f);
  return (u & 0x80000000u) ? ~u : (u | 0x80000000u);
}
__device__ __forceinline__ float fdec(unsigned k) {
  return (k & 0x80000000u) ? __uint_as_float(k & 0x7FFFFFFFu)
                           : __uint_as_float(~k);
}

// One packed weight column (32 x float2) . packed hidden vector -> packed (k,v).
// MACRO, not a function: h2 must never be address-taken so it stays in regs.
#define DOTCOL(RES, COLP, BIASV)                                              \
  do {                                                                        \
    unsigned long long _a0 = (BIASV), _a1 = 0ull, _a2 = 0ull, _a3 = 0ull;     \
    _Pragma("unroll")                                                         \
    for (int _t = 0; _t < 8; _t++) {                                          \
      ulonglong2 _wA = (COLP)[2 * _t];                                        \
      ulonglong2 _wB = (COLP)[2 * _t + 1];                                    \
      _a0 = ffma2(h2[4 * _t + 0], _wA.x, _a0);                                \
      _a1 = ffma2(h2[4 * _t + 1], _wA.y, _a1);                                \
      _a2 = ffma2(h2[4 * _t + 2], _wB.x, _a2);                                \
      _a3 = ffma2(h2[4 * _t + 3], _wB.y, _a3);                                \
    }                                                                         \
    (RES) = fadd2(fadd2(_a0, _a1), fadd2(_a2, _a3));                          \
  } while (0)

// ---------------------------------------------------------------------------
__global__ void zero_kernel() {
  int i = blockIdx.x * blockDim.x + threadIdx.x;
  if (i < KNODES * KD) g_upd[i] = 0.f;
  if (i < KNODES) {
    g_maxkey[i] = 0u;
    g_denom[i] = 0.f;
  }
  if (i < 40) g_stats[i] = 0.f;
}

// per-node query projection
__global__ void qnode_kernel(const float* __restrict__ atom,
                             const float* __restrict__ Wqs,
                             const float* __restrict__ Wqv) {
  int n = blockIdx.x * blockDim.x + threadIdx.x;
  if (n >= KNODES) return;
  const float* a = atom + (size_t)n * KD;
  float s[KNS], v[KNV * 3];
#pragma unroll
  for (int i = 0; i < KNS; i++) s[i] = a[i];
#pragma unroll
  for (int i = 0; i < KNV * 3; i++) v[i] = a[KNS + i];
  float* q = g_qnode + (size_t)n * KD;
#pragma unroll
  for (int o = 0; o < KNS; o++) {
    float acc = 0.f;
#pragma unroll
    for (int i = 0; i < KNS; i++) acc = fmaf(s[i], __ldg(&Wqs[i * KNS + o]), acc);
    q[o] = acc;
  }
#pragma unroll
  for (int o = 0; o < KNV; o++) {
    float a0 = 0.f, a1 = 0.f, a2 = 0.f;
#pragma unroll
    for (int i = 0; i < KNV; i++) {
      float w = __ldg(&Wqv[i * KNV + o]);
      a0 = fmaf(v[3 * i + 0], w, a0);
      a1 = fmaf(v[3 * i + 1], w, a1);
      a2 = fmaf(v[3 * i + 2], w, a2);
    }
    q[KNS + 3 * o + 0] = a0;
    q[KNS + 3 * o + 1] = a1;
    q[KNS + 3 * o + 2] = a2;
  }
}

// ---------------------------------------------------------------------------
// per-edge TP coefficients -> g_coef (transposed) + ef transpose -> g_efT.
// ---------------------------------------------------------------------------
__global__ void coef_kernel(const float* __restrict__ atom,
                            const float* __restrict__ shp,
                            const float* __restrict__ ef,
                            const int* __restrict__ eidx) {
  int e = blockIdx.x * blockDim.x + threadIdx.x;
  if (e >= KEDGES) return;
  const int dst = eidx[e];

  float4 sh4 = *(const float4*)(shp + 4 * (size_t)e);
  const float shs = sh4.x, s0 = sh4.y, s1 = sh4.z, s2 = sh4.w;

  const float4* ar = (const float4*)(atom + (size_t)dst * KD);
  float xs[KNS], xv[KNV * 3];
#pragma unroll
  for (int t = 0; t < 4; t++) {
    float4 w = ar[t];
    xs[4 * t + 0] = w.x; xs[4 * t + 1] = w.y;
    xs[4 * t + 2] = w.z; xs[4 * t + 3] = w.w;
  }
#pragma unroll
  for (int t = 0; t < 6; t++) {
    float4 w = ar[4 + t];
    xv[4 * t + 0] = w.x; xv[4 * t + 1] = w.y;
    xv[4 * t + 2] = w.z; xv[4 * t + 3] = w.w;
  }

  float* c = g_coef + e;     // column e; row stride KEDGES (coalesced per warp)
#pragma unroll
  for (int i = 0; i < 16; i++) c[(size_t)i * KEDGES] = xs[i] * shs;
#pragma unroll
  for (int i = 0; i < 8; i++) {
    float d = xv[3 * i] * s0 + xv[3 * i + 1] * s1 + xv[3 * i + 2] * s2;
    c[(size_t)(16 + i) * KEDGES] = KC110 * d;
  }
#pragma unroll
  for (int i = 0; i < 16; i++) {
    c[(size_t)(24 + 3 * i + 0) * KEDGES] = xs[i] * s0;
    c[(size_t)(24 + 3 * i + 1) * KEDGES] = xs[i] * s1;
    c[(size_t)(24 + 3 * i + 2) * KEDGES] = xs[i] * s2;
  }
#pragma unroll
  for (int i = 0; i < 8; i++) {
    c[(size_t)(72 + 3 * i + 0) * KEDGES] = shs * xv[3 * i + 0];
    c[(size_t)(72 + 3 * i + 1) * KEDGES] = shs * xv[3 * i + 1];
    c[(size_t)(72 + 3 * i + 2) * KEDGES] = shs * xv[3 * i + 2];
  }
#pragma unroll
  for (int i = 0; i < 8; i++) {
    float a0 = xv[3 * i], a1 = xv[3 * i + 1], a2 = xv[3 * i + 2];
    c[(size_t)(96 + 3 * i + 0) * KEDGES] = KC111 * (a1 * s2 - a2 * s1);
    c[(size_t)(96 + 3 * i + 1) * KEDGES] = KC111 * (a2 * s0 - a0 * s2);
    c[(size_t)(96 + 3 * i + 2) * KEDGES] = KC111 * (a0 * s1 - a1 * s0);
  }

  // ef row -> transposed [j][e]
  const float4* efr4 = (const float4*)(ef + (size_t)e * KHE);
#pragma unroll
  for (int t = 0; t < 8; t++) {
    float4 w = efr4[t];
    g_efT[(size_t)(4 * t + 0) * KEDGES + e] = w.x;
    g_efT[(size_t)(4 * t + 1) * KEDGES + e] = w.y;
    g_efT[(size_t)(4 * t + 2) * KEDGES + e] = w.z;
    g_efT[(size_t)(4 * t + 3) * KEDGES + e] = w.w;
  }
}

// ---------------------------------------------------------------------------
// fused per-edge kernel: dual MLP + o-outer packed TP epilogue.
// 512 threads/CTA (<=128 regs): h2 is the only big register array.
// All global traffic coalesced via transposed layouts.
// ---------------------------------------------------------------------------
__global__ void __launch_bounds__(NTHREADS, 1) edge_kernel(
    const float* __restrict__ kw1, const float* __restrict__ kb1,
    const float* __restrict__ kw2, const float* __restrict__ kb2,
    const float* __restrict__ vw1, const float* __restrict__ vb1,
    const float* __restrict__ vw2, const float* __restrict__ vb2) {
  extern __shared__ unsigned char smem[];
  float2* sP2f = (float2*)(smem);
  float2* sP1f = (float2*)(smem + SM_P1);
  float2* sB2f = (float2*)(smem + SM_B2);
  float2* sB1f = (float2*)(smem + SM_B1);

  int tid = threadIdx.x;
  for (int idx = tid; idx < KWN * KHE; idx += blockDim.x) {
    int p = idx >> 5, j = idx & 31;
    sP2f[idx] = make_float2(kw2[j * KWN + p], vw2[j * KWN + p]);
  }
  for (int idx = tid; idx < KHE * KHE; idx += blockDim.x)
    sP1f[idx] = make_float2(kw1[idx], vw1[idx]);
  for (int idx = tid; idx < KWN; idx += blockDim.x)
    sB2f[idx] = make_float2(kb2[idx], vb2[idx]);
  for (int idx = tid; idx < KHE; idx += blockDim.x)
    sB1f[idx] = make_float2(kb1[idx], vb1[idx]);
  __syncthreads();

  const ulonglong2* sP2 = (const ulonglong2*)sP2f;
  const ulonglong2* sP1 = (const ulonglong2*)sP1f;
  const unsigned long long* sB2u = (const unsigned long long*)sB2f;
  const unsigned long long* sB1u = (const unsigned long long*)sB1f;

  const int gstride = NBLOCKS * NTHREADS;
  for (int e = blockIdx.x * NTHREADS + tid; e < KEDGES; e += gstride) {
    // hidden layer, both MLPs packed; ef via coalesced transposed LDG
    unsigned long long h2[KHE];
#pragma unroll
    for (int o = 0; o < KHE; o++) h2[o] = sB1u[o];
    {
      const float* efc = g_efT + e;
      const ulonglong2* row = sP1;
#pragma unroll 1
      for (int j = 0; j < KHE; j++) {
        float fj = __ldg(efc + (size_t)j * KEDGES);
        unsigned long long fj2 = pk2(fj, fj);
#pragma unroll
        for (int t = 0; t < 16; t++) {
          ulonglong2 w = row[t];
          h2[2 * t + 0] = ffma2(fj2, w.x, h2[2 * t + 0]);
          h2[2 * t + 1] = ffma2(fj2, w.y, h2[2 * t + 1]);
        }
        row += 16;
      }
    }
#pragma unroll
    for (int o = 0; o < KHE; o++) {
      float a, b;
      upk2(h2[o], a, b);
      h2[o] = pk2(fmaxf(a, 0.f), fmaxf(b, 0.f));
    }

    const float* coef = g_coef + e;

    // s-part: o-outer, 1 packed accumulator; column p = ii*16 + o
#pragma unroll 1
    for (int o = 0; o < KNS; o++) {
      unsigned long long acc = 0ull;
      const ulonglong2* colp = sP2 + o * 16;
#pragma unroll 1
      for (int ii = 0; ii < 24; ii++) {
        unsigned long long w2;
        DOTCOL(w2, colp, sB2u[ii * 16 + o]);
        float cif = __ldg(coef + (size_t)ii * KEDGES);
        acc = ffma2(w2, pk2(cif, cif), acc);
        colp += 256;                       // 16 columns forward
      }
      float kk, vv;
      upk2(acc, kk, vv);
      g_kedge[(size_t)o * KEDGES + e] = kk;
      g_vedge[(size_t)o * KEDGES + e] = vv;
    }

    // v-part: o-outer, 3 packed accumulators; column p = 384 + jj*8 + o
#pragma unroll 1
    for (int o = 0; o < KNV; o++) {
      unsigned long long a0 = 0ull, a1 = 0ull, a2 = 0ull;
      const ulonglong2* colp = sP2 + (384 + o) * 16;
      const float* tc = coef + (size_t)24 * KEDGES;
#pragma unroll 1
      for (int jj = 0; jj < 32; jj++) {
        unsigned long long w2;
        DOTCOL(w2, colp, sB2u[384 + jj * 8 + o]);
        float f0 = __ldg(tc + (size_t)(3 * jj + 0) * KEDGES);
        float f1 = __ldg(tc + (size_t)(3 * jj + 1) * KEDGES);
        float f2 = __ldg(tc + (size_t)(3 * jj + 2) * KEDGES);
        a0 = ffma2(w2, pk2(f0, f0), a0);
        a1 = ffma2(w2, pk2(f1, f1), a1);
        a2 = ffma2(w2, pk2(f2, f2), a2);
        colp += 128;                       // 8 columns forward
      }
      float k0, v0, k1, v1, k2, v2;
      upk2(a0, k0, v0);
      upk2(a1, k1, v1);
      upk2(a2, k2, v2);
      int d = KNS + 3 * o;
      g_kedge[(size_t)(d + 0) * KEDGES + e] = k0;
      g_kedge[(size_t)(d + 1) * KEDGES + e] = k1;
      g_kedge[(size_t)(d + 2) * KEDGES + e] = k2;
      g_vedge[(size_t)(d + 0) * KEDGES + e] = v0;
      g_vedge[(size_t)(d + 1) * KEDGES + e] = v1;
      g_vedge[(size_t)(d + 2) * KEDGES + e] = v2;
    }
  }
}

// attn = q[src] . k[e]  (k transposed, coalesced) + segment max
__global__ void attn_kernel(const int* __restrict__ eidx) {
  int e = blockIdx.x * blockDim.x + threadIdx.x;
  if (e >= KEDGES) return;
  int src = eidx[KEDGES + e];
  const float4* q4 = (const float4*)(g_qnode + (size_t)src * KD);
  float acc = 0.f;
#pragma unroll
  for (int t = 0; t < 10; t++) {
    float4 qw = q4[t];
    acc = fmaf(__ldg(&g_kedge[(size_t)(4 * t + 0) * KEDGES + e]), qw.x, acc);
    acc = fmaf(__ldg(&g_kedge[(size_t)(4 * t + 1) * KEDGES + e]), qw.y, acc);
    acc = fmaf(__ldg(&g_kedge[(size_t)(4 * t + 2) * KEDGES + e]), qw.z, acc);
    acc = fmaf(__ldg(&g_kedge[(size_t)(4 * t + 3) * KEDGES + e]), qw.w, acc);
  }
  g_attn[e] = acc;
  atomicMax(&g_maxkey[src], fenc(acc));
}

// per-edge exp + denom accumulation
__global__ void eval_kernel(const int* __restrict__ eidx) {
  int e = blockIdx.x * blockDim.x + threadIdx.x;
  if (e >= KEDGES) return;
  int src = eidx[KEDGES + e];
  float m = fdec(g_maxkey[src]);
  float ex = expf(g_attn[e] - m);
  g_eval[e] = ex;
  atomicAdd(&g_denom[src], ex);
}

// scatter: 2D grid, blockIdx.y = dim; vedge transposed -> fully coalesced
__global__ void scatter_kernel(const int* __restrict__ eidx) {
  int e = blockIdx.x * blockDim.x + threadIdx.x;
  int d = blockIdx.y;
  if (e >= KEDGES) return;
  int src = __ldg(&eidx[KEDGES + e]);
  float ex = __ldg(&g_eval[e]);
  atomicAdd(&g_upd[(size_t)src * KD + d], ex * g_vedge[(size_t)d * KEDGES + e]);
}

// x = atom + upd/denom; accumulate batchnorm stats via warp shfl reduction
__global__ void nodeA_kernel(const float* __restrict__ atom) {
  int tid = threadIdx.x;
  int n = blockIdx.x * blockDim.x + tid;
  float x[KD];
  if (n < KNODES) {
    float den = g_denom[n];
    float inv = den > 0.f ? 1.f / den : 0.f;
#pragma unroll
    for (int d = 0; d < KD; d++) {
      float xv_ = atom[(size_t)n * KD + d] + g_upd[(size_t)n * KD + d] * inv;
      x[d] = xv_;
      g_upd[(size_t)n * KD + d] = xv_;
    }
  } else {
#pragma unroll
    for (int d = 0; d < KD; d++) x[d] = 0.f;
  }
  float st[40];
#pragma unroll
  for (int c = 0; c < 16; c++) {
    st[c] = x[c];
    st[16 + c] = x[c] * x[c];
  }
#pragma unroll
  for (int c = 0; c < 8; c++) {
    float v0 = x[16 + 3 * c], v1 = x[16 + 3 * c + 1], v2 = x[16 + 3 * c + 2];
    st[32 + c] = v0 * v0 + v1 * v1 + v2 * v2;
  }
#pragma unroll
  for (int c = 0; c < 40; c++) {
#pragma unroll
    for (int off = 16; off > 0; off >>= 1)
      st[c] += __shfl_down_sync(0xFFFFFFFFu, st[c], off);
  }
  if ((tid & 31) == 0) {
#pragma unroll
    for (int c = 0; c < 40; c++) atomicAdd(&g_stats[c], st[c]);
  }
}

// batchnorm apply -> d_out node section
__global__ void nodeB_kernel(const float* __restrict__ bnws,
                             const float* __restrict__ bnbs,
                             const float* __restrict__ bnwv,
                             float* __restrict__ out) {
  int n = blockIdx.x * blockDim.x + threadIdx.x;
  if (n >= KNODES) return;
  const float invN = 1.f / (float)KNODES;
  const float* x = g_upd + (size_t)n * KD;
  float* o = out + (size_t)n * KD;
#pragma unroll
  for (int c = 0; c < 16; c++) {
    float mu = g_stats[c] * invN;
    float var = g_stats[16 + c] * invN - mu * mu;
    o[c] = (x[c] - mu) * rsqrtf(var + KEPS) * __ldg(&bnws[c]) + __ldg(&bnbs[c]);
  }
#pragma unroll
  for (int c = 0; c < 8; c++) {
    float norm = g_stats[32 + c] * (invN / 3.f);
    float sc = rsqrtf(norm + KEPS) * __ldg(&bnwv[c]);
    o[16 + 3 * c + 0] = x[16 + 3 * c + 0] * sc;
    o[16 + 3 * c + 1] = x[16 + 3 * c + 1] * sc;
    o[16 + 3 * c + 2] = x[16 + 3 * c + 2] * sc;
  }
}

// copy edge_features into the second output slot
__global__ void copy_kernel(const float* __restrict__ ef, float* __restrict__ out) {
  int i = blockIdx.x * blockDim.x + threadIdx.x;
  const float4* s = (const float4*)ef;
  float4* d = (float4*)out;
  int n4 = (KEDGES * KHE) / 4;
  if (i < n4) d[i] = s[i];
}

extern "C" void kernel_launch(void* const* d_in, const int* in_sizes, int n_in,
                              void* d_out, int out_size) {
  const float* atom = (const float*)d_in[0];
  const float* ef   = (const float*)d_in[1];
  const float* shp  = (const float*)d_in[2];
  const float* Wqs  = (const float*)d_in[3];
  const float* Wqv  = (const float*)d_in[4];
  const float* kw1  = (const float*)d_in[5];
  const float* kb1  = (const float*)d_in[6];
  const float* kw2  = (const float*)d_in[7];
  const float* kb2  = (const float*)d_in[8];
  const float* vw1  = (const float*)d_in[9];
  const float* vb1  = (const float*)d_in[10];
  const float* vw2  = (const float*)d_in[11];
  const float* vb2  = (const float*)d_in[12];
  const float* bnws = (const float*)d_in[13];
  const float* bnbs = (const float*)d_in[14];
  const float* bnwv = (const float*)d_in[15];
  const int*   eidx = (const int*)d_in[16];
  float* out = (float*)d_out;

  cudaFuncSetAttribute(edge_kernel, cudaFuncAttributeMaxDynamicSharedMemorySize,
                       SM_BYTES);

  zero_kernel<<<(KNODES * KD + 255) / 256, 256>>>();
  qnode_kernel<<<(KNODES + 255) / 256, 256>>>(atom, Wqs, Wqv);
  coef_kernel<<<(KEDGES + 255) / 256, 256>>>(atom, shp, ef, eidx);  // launch #3
  edge_kernel<<<NBLOCKS, NTHREADS, SM_BYTES>>>(kw1, kb1, kw2, kb2,
                                               vw1, vb1, vw2, vb2); // launch #4 (ncu)
  attn_kernel<<<(KEDGES + 255) / 256, 256>>>(eidx);
  eval_kernel<<<(KEDGES + 255) / 256, 256>>>(eidx);
  {
    dim3 g((KEDGES + 255) / 256, KD);
    scatter_kernel<<<g, 256>>>(eidx);
  }
  nodeA_kernel<<<(KNODES + 255) / 256, 256>>>(atom);
  nodeB_kernel<<<(KNODES + 255) / 256, 256>>>(bnws, bnbs, bnwv, out);
  copy_kernel<<<(KEDGES * KHE / 4 + 255) / 256, 256>>>(ef, out + KNODES * KD);
}

// round 9
// speedup vs baseline: 1.0426x; 1.0426x over previous
#include <cuda_runtime.h>
#include <cstdint>

#define KNS 16
#define KNV 8
#define KHE 32
#define KD  40
#define KWN 640
#define KNODES 10000
#define KEDGES 160000
#define KC110 0.5773502691896258f
#define KC111 0.7071067811865476f
#define KEPS  1e-5f

#define ETILE   64
#define NTILES  (KEDGES / ETILE)      // 2500
#define NTHREADS 256
#define NBLOCKS  148

// shared memory layout (bytes)
#define SMB_W2 0                      // 640 cols x 32 ull (reordered)   163840
#define SMB_P1 163840                 // 32 x 32 float2                    8192
#define SMB_B2 172032                 // 640 ull (reordered)               5120
#define SMB_B1 177152                 // 32 ull                             256
#define SMB_H  177408                 // h-tile 32 x 64 ull               16384
#define SMB_TOT 193792

typedef unsigned long long ull;

// ---------------------------------------------------------------------------
// device scratch (static -- no cudaMalloc allowed)
// ---------------------------------------------------------------------------
__device__ float    g_qnode[KNODES * KD];
__device__ float    g_attn[KEDGES];
__device__ float    g_eval[KEDGES];
__device__ float    g_kedge[KD * KEDGES];   // TRANSPOSED [d][e]
__device__ float    g_vedge[KD * KEDGES];   // TRANSPOSED [d][e]
__device__ float    g_efT[KHE * KEDGES];    // TRANSPOSED [j][e]
__device__ unsigned g_maxkey[KNODES];
__device__ float    g_denom[KNODES];
__device__ float    g_upd[KNODES * KD];
__device__ float    g_stats[40];
// per-edge TP coefficients, TRANSPOSED [coef][edge]: rows 0..23 cA, 24..119 tB
__device__ float    g_coef[120 * KEDGES];

// ---------------------------------------------------------------------------
// packed f32x2 helpers (FFMA2 only reachable via PTX)
// ---------------------------------------------------------------------------
__device__ __forceinline__ ull ffma2(ull a, ull b, ull c) {
  ull d;
  asm("fma.rn.f32x2 %0, %1, %2, %3;" : "=l"(d) : "l"(a), "l"(b), "l"(c));
  return d;
}
__device__ __forceinline__ ull pk2(float lo, float hi) {
  ull r;
  asm("mov.b64 %0, {%1, %2};" : "=l"(r) : "f"(lo), "f"(hi));
  return r;
}
__device__ __forceinline__ void upk2(ull v, float& lo, float& hi) {
  asm("mov.b64 {%0, %1}, %2;" : "=f"(lo), "=f"(hi) : "l"(v));
}

// orderable-uint encoding for float atomicMax
__device__ __forceinline__ unsigned fenc(float f) {
  unsigned u = __float_as_uint(f);
  return (u & 0x80000000u) ? ~u : (u | 0x80000000u);
}
__device__ __forceinline__ float fdec(unsigned k) {
  return (k & 0x80000000u) ? __uint_as_float(k & 0x7FFFFFFFu)
                           : __uint_as_float(~k);
}

// reordered col index -> original packed column p of the 640-wide layer-2
__device__ __forceinline__ int cidx_to_p(int cidx) {
  if (cidx < 384) {
    int o = cidx / 24, ii = cidx - o * 24;
    return ii * 16 + o;
  }
  int c = cidx - 384;
  int o = c >> 5, jj = c & 31;
  return 384 + jj * 8 + o;
}

// ---------------------------------------------------------------------------
__global__ void zero_kernel() {
  int i = blockIdx.x * blockDim.x + threadIdx.x;
  if (i < KNODES * KD) g_upd[i] = 0.f;
  if (i < KNODES) {
    g_maxkey[i] = 0u;
    g_denom[i] = 0.f;
  }
  if (i < 40) g_stats[i] = 0.f;
}

// per-node query projection
__global__ void qnode_kernel(const float* __restrict__ atom,
                             const float* __restrict__ Wqs,
                             const float* __restrict__ Wqv) {
  int n = blockIdx.x * blockDim.x + threadIdx.x;
  if (n >= KNODES) return;
  const float* a = atom + (size_t)n * KD;
  float s[KNS], v[KNV * 3];
#pragma unroll
  for (int i = 0; i < KNS; i++) s[i] = a[i];
#pragma unroll
  for (int i = 0; i < KNV * 3; i++) v[i] = a[KNS + i];
  float* q = g_qnode + (size_t)n * KD;
#pragma unroll
  for (int o = 0; o < KNS; o++) {
    float acc = 0.f;
#pragma unroll
    for (int i = 0; i < KNS; i++) acc = fmaf(s[i], __ldg(&Wqs[i * KNS + o]), acc);
    q[o] = acc;
  }
#pragma unroll
  for (int o = 0; o < KNV; o++) {
    float a0 = 0.f, a1 = 0.f, a2 = 0.f;
#pragma unroll
    for (int i = 0; i < KNV; i++) {
      float w = __ldg(&Wqv[i * KNV + o]);
      a0 = fmaf(v[3 * i + 0], w, a0);
      a1 = fmaf(v[3 * i + 1], w, a1);
      a2 = fmaf(v[3 * i + 2], w, a2);
    }
    q[KNS + 3 * o + 0] = a0;
    q[KNS + 3 * o + 1] = a1;
    q[KNS + 3 * o + 2] = a2;
  }
}

// ---------------------------------------------------------------------------
// per-edge TP coefficients -> g_coef (transposed) + ef transpose -> g_efT
// ---------------------------------------------------------------------------
__global__ void coef_kernel(const float* __restrict__ atom,
                            const float* __restrict__ shp,
                            const float* __restrict__ ef,
                            const int* __restrict__ eidx) {
  int e = blockIdx.x * blockDim.x + threadIdx.x;
  if (e >= KEDGES) return;
  const int dst = eidx[e];

  float4 sh4 = *(const float4*)(shp + 4 * (size_t)e);
  const float shs = sh4.x, s0 = sh4.y, s1 = sh4.z, s2 = sh4.w;

  const float4* ar = (const float4*)(atom + (size_t)dst * KD);
  float xs[KNS], xv[KNV * 3];
#pragma unroll
  for (int t = 0; t < 4; t++) {
    float4 w = ar[t];
    xs[4 * t + 0] = w.x; xs[4 * t + 1] = w.y;
    xs[4 * t + 2] = w.z; xs[4 * t + 3] = w.w;
  }
#pragma unroll
  for (int t = 0; t < 6; t++) {
    float4 w = ar[4 + t];
    xv[4 * t + 0] = w.x; xv[4 * t + 1] = w.y;
    xv[4 * t + 2] = w.z; xv[4 * t + 3] = w.w;
  }

  float* c = g_coef + e;
#pragma unroll
  for (int i = 0; i < 16; i++) c[(size_t)i * KEDGES] = xs[i] * shs;
#pragma unroll
  for (int i = 0; i < 8; i++) {
    float d = xv[3 * i] * s0 + xv[3 * i + 1] * s1 + xv[3 * i + 2] * s2;
    c[(size_t)(16 + i) * KEDGES] = KC110 * d;
  }
#pragma unroll
  for (int i = 0; i < 16; i++) {
    c[(size_t)(24 + 3 * i + 0) * KEDGES] = xs[i] * s0;
    c[(size_t)(24 + 3 * i + 1) * KEDGES] = xs[i] * s1;
    c[(size_t)(24 + 3 * i + 2) * KEDGES] = xs[i] * s2;
  }
#pragma unroll
  for (int i = 0; i < 8; i++) {
    c[(size_t)(72 + 3 * i + 0) * KEDGES] = shs * xv[3 * i + 0];
    c[(size_t)(72 + 3 * i + 1) * KEDGES] = shs * xv[3 * i + 1];
    c[(size_t)(72 + 3 * i + 2) * KEDGES] = shs * xv[3 * i + 2];
  }
#pragma unroll
  for (int i = 0; i < 8; i++) {
    float a0 = xv[3 * i], a1 = xv[3 * i + 1], a2 = xv[3 * i + 2];
    c[(size_t)(96 + 3 * i + 0) * KEDGES] = KC111 * (a1 * s2 - a2 * s1);
    c[(size_t)(96 + 3 * i + 1) * KEDGES] = KC111 * (a2 * s0 - a0 * s2);
    c[(size_t)(96 + 3 * i + 2) * KEDGES] = KC111 * (a0 * s1 - a1 * s0);
  }

  const float4* efr4 = (const float4*)(ef + (size_t)e * KHE);
#pragma unroll
  for (int t = 0; t < 8; t++) {
    float4 w = efr4[t];
    g_efT[(size_t)(4 * t + 0) * KEDGES + e] = w.x;
    g_efT[(size_t)(4 * t + 1) * KEDGES + e] = w.y;
    g_efT[(size_t)(4 * t + 2) * KEDGES + e] = w.z;
    g_efT[(size_t)(4 * t + 3) * KEDGES + e] = w.w;
  }
}

// ---------------------------------------------------------------------------
// block-cooperative dual-MLP + TP: 64-edge tiles, h-tile in smem, weight LDS
// shared across each thread's 4 (or 2) edges. Persistent grid.
// ---------------------------------------------------------------------------
__global__ void __launch_bounds__(NTHREADS, 1) edge_kernel(
    const float* __restrict__ kw1, const float* __restrict__ kb1,
    const float* __restrict__ kw2, const float* __restrict__ kb2,
    const float* __restrict__ vw1, const float* __restrict__ vb1,
    const float* __restrict__ vw2, const float* __restrict__ vb2) {
  extern __shared__ unsigned char smem[];
  ull*  sW2 = (ull*)(smem + SMB_W2);
  float2* sP1f = (float2*)(smem + SMB_P1);
  ull*  sB2 = (ull*)(smem + SMB_B2);
  ull*  sB1 = (ull*)(smem + SMB_B1);
  ull*  sH  = (ull*)(smem + SMB_H);
  const ulonglong2* sP1 = (const ulonglong2*)sP1f;

  const int tid = threadIdx.x;
  // ---- load + reorder weights (once per block) ----
  for (int idx = tid; idx < KWN * KHE; idx += NTHREADS) {
    int cidx = idx >> 5, j = idx & 31;
    int p = cidx_to_p(cidx);
    sW2[idx] = pk2(kw2[j * KWN + p], vw2[j * KWN + p]);
  }
  for (int idx = tid; idx < KWN; idx += NTHREADS) {
    int p = cidx_to_p(idx);
    sB2[idx] = pk2(kb2[p], vb2[p]);
  }
  for (int idx = tid; idx < KHE * KHE; idx += NTHREADS)
    sP1f[idx] = make_float2(kw1[idx], vw1[idx]);
  for (int idx = tid; idx < KHE; idx += NTHREADS)
    sB1[idx] = pk2(kb1[idx], vb1[idx]);
  __syncthreads();

  // decompositions for the three phases
  const int eA  = tid >> 2;            // phase A: edge-in-tile (0..63)
  const int octA = tid & 3;            // phase A: hidden octet
  const int oS  = tid >> 4;            // phase B-s: s-output (0..15)
  const int egS = (tid & 15) * 4;      // phase B-s: edge base (4 edges)
  const int oV  = tid >> 5;            // phase B-v: v-output (0..7)
  const int egV = (tid & 31) * 2;      // phase B-v: edge base (2 edges)

  for (int tile = blockIdx.x; tile < NTILES; tile += NBLOCKS) {
    const int e0 = tile * ETILE;

    // ---- Phase A: hidden layer -> smem h-tile [j][64 edges] ----
    {
      ull h[8];
#pragma unroll
      for (int m = 0; m < 8; m++) h[m] = sB1[octA * 8 + m];
      const float* efc = g_efT + (e0 + eA);
      const ulonglong2* rowb = sP1 + octA * 4;
#pragma unroll 4
      for (int j = 0; j < KHE; j++) {
        float fj = __ldg(efc + (size_t)j * KEDGES);
        ull fj2 = pk2(fj, fj);
        const ulonglong2* row = rowb + j * 16;
#pragma unroll
        for (int t = 0; t < 4; t++) {
          ulonglong2 w = row[t];
          h[2 * t + 0] = ffma2(fj2, w.x, h[2 * t + 0]);
          h[2 * t + 1] = ffma2(fj2, w.y, h[2 * t + 1]);
        }
      }
#pragma unroll
      for (int m = 0; m < 8; m++) {
        float a, b;
        upk2(h[m], a, b);
        sH[(octA * 8 + m) * ETILE + eA] = pk2(fmaxf(a, 0.f), fmaxf(b, 0.f));
      }
    }
    __syncthreads();

    // ---- Phase B-s: s outputs (o = 0..15), 4 edges/thread ----
    {
      ull outa0 = 0ull, outa1 = 0ull, outa2 = 0ull, outa3 = 0ull;
#pragma unroll 1
      for (int oct = 0; oct < 3; oct++) {
        const int cb = oS * 24 + oct * 8;      // first col of this octet
        ull C2[8][4];
#pragma unroll
        for (int c = 0; c < 8; c++) {
          ull b = sB2[cb + c];
          C2[c][0] = b; C2[c][1] = b; C2[c][2] = b; C2[c][3] = b;
        }
        const ull* wbase = sW2 + cb * 32;
#pragma unroll 1
        for (int j = 0; j < KHE; j++) {
          ulonglong2 hA = *(const ulonglong2*)(sH + j * ETILE + egS);
          ulonglong2 hB = *(const ulonglong2*)(sH + j * ETILE + egS + 2);
#pragma unroll
          for (int c = 0; c < 8; c++) {
            ull w = wbase[c * 32 + j];
            C2[c][0] = ffma2(hA.x, w, C2[c][0]);
            C2[c][1] = ffma2(hA.y, w, C2[c][1]);
            C2[c][2] = ffma2(hB.x, w, C2[c][2]);
            C2[c][3] = ffma2(hB.y, w, C2[c][3]);
          }
        }
#pragma unroll
        for (int c = 0; c < 8; c++) {
          int ii = oct * 8 + c;
          float4 cv = *(const float4*)(g_coef + (size_t)ii * KEDGES + e0 + egS);
          outa0 = ffma2(C2[c][0], pk2(cv.x, cv.x), outa0);
          outa1 = ffma2(C2[c][1], pk2(cv.y, cv.y), outa1);
          outa2 = ffma2(C2[c][2], pk2(cv.z, cv.z), outa2);
          outa3 = ffma2(C2[c][3], pk2(cv.w, cv.w), outa3);
        }
      }
      float k0, v0, k1, v1, k2, v2, k3, v3;
      upk2(outa0, k0, v0); upk2(outa1, k1, v1);
      upk2(outa2, k2, v2); upk2(outa3, k3, v3);
      float* kp = g_kedge + (size_t)oS * KEDGES + e0 + egS;
      float* vp = g_vedge + (size_t)oS * KEDGES + e0 + egS;
      *(float4*)kp = make_float4(k0, k1, k2, k3);
      *(float4*)vp = make_float4(v0, v1, v2, v3);
    }

    // ---- Phase B-v: v outputs (o = 0..7), 2 edges/thread ----
    {
      ull ov0a = 0ull, ov0b = 0ull, ov1a = 0ull, ov1b = 0ull,
          ov2a = 0ull, ov2b = 0ull;
#pragma unroll 1
      for (int oct = 0; oct < 4; oct++) {
        const int cb = 384 + oV * 32 + oct * 8;
        ull C2[8][2];
#pragma unroll
        for (int c = 0; c < 8; c++) {
          ull b = sB2[cb + c];
          C2[c][0] = b; C2[c][1] = b;
        }
        const ull* wbase = sW2 + cb * 32;
#pragma unroll 1
        for (int j = 0; j < KHE; j++) {
          ulonglong2 hA = *(const ulonglong2*)(sH + j * ETILE + egV);
#pragma unroll
          for (int c = 0; c < 8; c++) {
            ull w = wbase[c * 32 + j];
            C2[c][0] = ffma2(hA.x, w, C2[c][0]);
            C2[c][1] = ffma2(hA.y, w, C2[c][1]);
          }
        }
#pragma unroll
        for (int c = 0; c < 8; c++) {
          int jj = oct * 8 + c;
          const float* tb = g_coef + (size_t)(24 + 3 * jj) * KEDGES + e0 + egV;
          float2 t0 = *(const float2*)(tb);
          float2 t1 = *(const float2*)(tb + (size_t)KEDGES);
          float2 t2 = *(const float2*)(tb + (size_t)2 * KEDGES);
          ov0a = ffma2(C2[c][0], pk2(t0.x, t0.x), ov0a);
          ov0b = ffma2(C2[c][1], pk2(t0.y, t0.y), ov0b);
          ov1a = ffma2(C2[c][0], pk2(t1.x, t1.x), ov1a);
          ov1b = ffma2(C2[c][1], pk2(t1.y, t1.y), ov1b);
          ov2a = ffma2(C2[c][0], pk2(t2.x, t2.x), ov2a);
          ov2b = ffma2(C2[c][1], pk2(t2.y, t2.y), ov2b);
        }
      }
      const int d0 = KNS + 3 * oV;
      float ka, va, kb, vb;
      upk2(ov0a, ka, va); upk2(ov0b, kb, vb);
      *(float2*)(g_kedge + (size_t)(d0 + 0) * KEDGES + e0 + egV) = make_float2(ka, kb);
      *(float2*)(g_vedge + (size_t)(d0 + 0) * KEDGES + e0 + egV) = make_float2(va, vb);
      upk2(ov1a, ka, va); upk2(ov1b, kb, vb);
      *(float2*)(g_kedge + (size_t)(d0 + 1) * KEDGES + e0 + egV) = make_float2(ka, kb);
      *(float2*)(g_vedge + (size_t)(d0 + 1) * KEDGES + e0 + egV) = make_float2(va, vb);
      upk2(ov2a, ka, va); upk2(ov2b, kb, vb);
      *(float2*)(g_kedge + (size_t)(d0 + 2) * KEDGES + e0 + egV) = make_float2(ka, kb);
      *(float2*)(g_vedge + (size_t)(d0 + 2) * KEDGES + e0 + egV) = make_float2(va, vb);
    }
    __syncthreads();   // protect sH before next tile overwrites it
  }
}

// attn = q[src] . k[e]  (k transposed, coalesced) + segment max
__global__ void attn_kernel(const int* __restrict__ eidx) {
  int e = blockIdx.x * blockDim.x + threadIdx.x;
  if (e >= KEDGES) return;
  int src = eidx[KEDGES + e];
  const float4* q4 = (const float4*)(g_qnode + (size_t)src * KD);
  float acc = 0.f;
#pragma unroll
  for (int t = 0; t < 10; t++) {
    float4 qw = q4[t];
    acc = fmaf(__ldg(&g_kedge[(size_t)(4 * t + 0) * KEDGES + e]), qw.x, acc);
    acc = fmaf(__ldg(&g_kedge[(size_t)(4 * t + 1) * KEDGES + e]), qw.y, acc);
    acc = fmaf(__ldg(&g_kedge[(size_t)(4 * t + 2) * KEDGES + e]), qw.z, acc);
    acc = fmaf(__ldg(&g_kedge[(size_t)(4 * t + 3) * KEDGES + e]), qw.w, acc);
  }
  g_attn[e] = acc;
  atomicMax(&g_maxkey[src], fenc(acc));
}

// per-edge exp + denom accumulation
__global__ void eval_kernel(const int* __restrict__ eidx) {
  int e = blockIdx.x * blockDim.x + threadIdx.x;
  if (e >= KEDGES) return;
  int src = eidx[KEDGES + e];
  float m = fdec(g_maxkey[src]);
  float ex = expf(g_attn[e] - m);
  g_eval[e] = ex;
  atomicAdd(&g_denom[src], ex);
}

// scatter: 2D grid, blockIdx.y = dim; vedge transposed -> fully coalesced
__global__ void scatter_kernel(const int* __restrict__ eidx) {
  int e = blockIdx.x * blockDim.x + threadIdx.x;
  int d = blockIdx.y;
  if (e >= KEDGES) return;
  int src = __ldg(&eidx[KEDGES + e]);
  float ex = __ldg(&g_eval[e]);
  atomicAdd(&g_upd[(size_t)src * KD + d], ex * g_vedge[(size_t)d * KEDGES + e]);
}

// x = atom + upd/denom; accumulate batchnorm stats via warp shfl reduction
__global__ void nodeA_kernel(const float* __restrict__ atom) {
  int tid = threadIdx.x;
  int n = blockIdx.x * blockDim.x + tid;
  float x[KD];
  if (n < KNODES) {
    float den = g_denom[n];
    float inv = den > 0.f ? 1.f / den : 0.f;
#pragma unroll
    for (int d = 0; d < KD; d++) {
      float xv_ = atom[(size_t)n * KD + d] + g_upd[(size_t)n * KD + d] * inv;
      x[d] = xv_;
      g_upd[(size_t)n * KD + d] = xv_;
    }
  } else {
#pragma unroll
    for (int d = 0; d < KD; d++) x[d] = 0.f;
  }
  float st[40];
#pragma unroll
  for (int c = 0; c < 16; c++) {
    st[c] = x[c];
    st[16 + c] = x[c] * x[c];
  }
#pragma unroll
  for (int c = 0; c < 8; c++) {
    float v0 = x[16 + 3 * c], v1 = x[16 + 3 * c + 1], v2 = x[16 + 3 * c + 2];
    st[32 + c] = v0 * v0 + v1 * v1 + v2 * v2;
  }
#pragma unroll
  for (int c = 0; c < 40; c++) {
#pragma unroll
    for (int off = 16; off > 0; off >>= 1)
      st[c] += __shfl_down_sync(0xFFFFFFFFu, st[c], off);
  }
  if ((tid & 31) == 0) {
#pragma unroll
    for (int c = 0; c < 40; c++) atomicAdd(&g_stats[c], st[c]);
  }
}

// batchnorm apply -> d_out node section
__global__ void nodeB_kernel(const float* __restrict__ bnws,
                             const float* __restrict__ bnbs,
                             const float* __restrict__ bnwv,
                             float* __restrict__ out) {
  int n = blockIdx.x * blockDim.x + threadIdx.x;
  if (n >= KNODES) return;
  const float invN = 1.f / (float)KNODES;
  const float* x = g_upd + (size_t)n * KD;
  float* o = out + (size_t)n * KD;
#pragma unroll
  for (int c = 0; c < 16; c++) {
    float mu = g_stats[c] * invN;
    float var = g_stats[16 + c] * invN - mu * mu;
    o[c] = (x[c] - mu) * rsqrtf(var + KEPS) * __ldg(&bnws[c]) + __ldg(&bnbs[c]);
  }
#pragma unroll
  for (int c = 0; c < 8; c++) {
    float norm = g_stats[32 + c] * (invN / 3.f);
    float sc = rsqrtf(norm + KEPS) * __ldg(&bnwv[c]);
    o[16 + 3 * c + 0] = x[16 + 3 * c + 0] * sc;
    o[16 + 3 * c + 1] = x[16 + 3 * c + 1] * sc;
    o[16 + 3 * c + 2] = x[16 + 3 * c + 2] * sc;
  }
}

// copy edge_features into the second output slot
__global__ void copy_kernel(const float* __restrict__ ef, float* __restrict__ out) {
  int i = blockIdx.x * blockDim.x + threadIdx.x;
  const float4* s = (const float4*)ef;
  float4* d = (float4*)out;
  int n4 = (KEDGES * KHE) / 4;
  if (i < n4) d[i] = s[i];
}

extern "C" void kernel_launch(void* const* d_in, const int* in_sizes, int n_in,
                              void* d_out, int out_size) {
  const float* atom = (const float*)d_in[0];
  const float* ef   = (const float*)d_in[1];
  const float* shp  = (const float*)d_in[2];
  const float* Wqs  = (const float*)d_in[3];
  const float* Wqv  = (const float*)d_in[4];
  const float* kw1  = (const float*)d_in[5];
  const float* kb1  = (const float*)d_in[6];
  const float* kw2  = (const float*)d_in[7];
  const float* kb2  = (const float*)d_in[8];
  const float* vw1  = (const float*)d_in[9];
  const float* vb1  = (const float*)d_in[10];
  const float* vw2  = (const float*)d_in[11];
  const float* vb2  = (const float*)d_in[12];
  const float* bnws = (const float*)d_in[13];
  const float* bnbs = (const float*)d_in[14];
  const float* bnwv = (const float*)d_in[15];
  const int*   eidx = (const int*)d_in[16];
  float* out = (float*)d_out;

  cudaFuncSetAttribute(edge_kernel, cudaFuncAttributeMaxDynamicSharedMemorySize,
                       SMB_TOT);

  zero_kernel<<<(KNODES * KD + 255) / 256, 256>>>();
  qnode_kernel<<<(KNODES + 255) / 256, 256>>>(atom, Wqs, Wqv);
  coef_kernel<<<(KEDGES + 255) / 256, 256>>>(atom, shp, ef, eidx);  // launch #3
  edge_kernel<<<NBLOCKS, NTHREADS, SMB_TOT>>>(kw1, kb1, kw2, kb2,
                                              vw1, vb1, vw2, vb2);  // launch #4 (ncu)
  attn_kernel<<<(KEDGES + 255) / 256, 256>>>(eidx);
  eval_kernel<<<(KEDGES + 255) / 256, 256>>>(eidx);
  {
    dim3 g((KEDGES + 255) / 256, KD);
    scatter_kernel<<<g, 256>>>(eidx);
  }
  nodeA_kernel<<<(KNODES + 255) / 256, 256>>>(atom);
  nodeB_kernel<<<(KNODES + 255) / 256, 256>>>(bnws, bnbs, bnwv, out);
  copy_kernel<<<(KEDGES * KHE / 4 + 255) / 256, 256>>>(ef, out + KNODES * KD);
}